// round 9
// baseline (speedup 1.0000x reference)
#include <cuda_runtime.h>

// Problem constants (fixed by the dataset)
#define B_ROWS 4096
#define DIM_IN 128
#define H_DIM  512
#define D_DIM  256
#define M_CON  64
#define N_ITER 100
#define TR     32          // rows per block in the iteration kernel
#define ITHREADS 512       // threads in the iteration kernel

// Scratch (device globals: no allocation allowed)
__device__ float g_h1[B_ROWS * H_DIM];
__device__ float g_h2[B_ROWS * H_DIM];
__device__ float g_y0[B_ROWS * D_DIM];
__device__ float g_Ginv[M_CON * M_CON];
__device__ float g_MopNeg[M_CON * D_DIM];   // stores -K A (pre-negated)

// ---------------------------------------------------------------------------
// Packed fp32x2 helpers (SASS FFMA2 — ptxas never auto-generates these)
// ---------------------------------------------------------------------------
__device__ __forceinline__ unsigned long long pack2(float lo, float hi) {
    unsigned long long r;
    asm("mov.b64 %0, {%1, %2};" : "=l"(r) : "f"(lo), "f"(hi));
    return r;
}
__device__ __forceinline__ unsigned long long dup2(float v) {
    unsigned long long r;
    asm("mov.b64 %0, {%1, %1};" : "=l"(r) : "f"(v));
    return r;
}
__device__ __forceinline__ void fma2(unsigned long long& d,
                                     unsigned long long a,
                                     unsigned long long b) {
    asm("fma.rn.f32x2 %0, %1, %2, %0;" : "+l"(d) : "l"(a), "l"(b));
}
__device__ __forceinline__ void unpack2(unsigned long long v, float& lo, float& hi) {
    asm("mov.b64 {%0, %1}, %2;" : "=f"(lo), "=f"(hi) : "l"(v));
}

// ---------------------------------------------------------------------------
// Register-blocked SGEMM with packed FFMA2: C = act(X @ W + bias)
// BM=128, BN=64, BK=16, 256 threads, 8x4 per thread (8 rows x 2 f32x2 pairs).
// Small tiles -> 256-block grids that fill 148 SMs, and 3-4 blocks/SM resident.
// ---------------------------------------------------------------------------
__global__ __launch_bounds__(256) void gemm_bias_act(
    const float* __restrict__ X, const float* __restrict__ W,
    const float* __restrict__ bias, float* __restrict__ C,
    int M, int N, int K, int doRelu)
{
    __shared__ float Xs[16][128];   // transposed: Xs[k][m]
    __shared__ float Ws[16][64];    // row-major:  Ws[k][n]

    const int tid  = threadIdx.x;
    const int brow = blockIdx.y * 128;
    const int bcol = blockIdx.x * 64;
    const int tx   = tid & 15;   // n-dir: cols tx*4 .. tx*4+3
    const int ty   = tid >> 4;   // m-dir: rows ty*8 .. ty*8+7

    // load mapping
    const int xr0 = tid >> 2;          // 0..63  (+64 for second)
    const int xc0 = (tid & 3) * 4;     // 0,4,8,12
    const int wr0 = tid >> 4;          // 0..15
    const int wc0 = (tid & 15) * 4;    // 0..60

    unsigned long long acc2[8][2];
    #pragma unroll
    for (int i = 0; i < 8; i++) { acc2[i][0] = 0ULL; acc2[i][1] = 0ULL; }

    for (int kt = 0; kt < K; kt += 16) {
        float4 xv0 = *(const float4*)&X[(size_t)(brow + xr0) * K + kt + xc0];
        float4 xv1 = *(const float4*)&X[(size_t)(brow + xr0 + 64) * K + kt + xc0];
        float4 wv  = *(const float4*)&W[(size_t)(kt + wr0) * N + bcol + wc0];

        Xs[xc0 + 0][xr0] = xv0.x;  Xs[xc0 + 1][xr0] = xv0.y;
        Xs[xc0 + 2][xr0] = xv0.z;  Xs[xc0 + 3][xr0] = xv0.w;
        Xs[xc0 + 0][xr0 + 64] = xv1.x;  Xs[xc0 + 1][xr0 + 64] = xv1.y;
        Xs[xc0 + 2][xr0 + 64] = xv1.z;  Xs[xc0 + 3][xr0 + 64] = xv1.w;
        *(float4*)&Ws[wr0][wc0] = wv;
        __syncthreads();

        #pragma unroll
        for (int k = 0; k < 16; k++) {
            float a[8];
            float4 a0 = *(const float4*)&Xs[k][ty * 8];
            float4 a1 = *(const float4*)&Xs[k][ty * 8 + 4];
            a[0]=a0.x; a[1]=a0.y; a[2]=a0.z; a[3]=a0.w;
            a[4]=a1.x; a[5]=a1.y; a[6]=a1.z; a[7]=a1.w;
            ulonglong2 bv = *(const ulonglong2*)&Ws[k][tx * 4];
            #pragma unroll
            for (int i = 0; i < 8; i++) {
                unsigned long long ad = dup2(a[i]);
                fma2(acc2[i][0], ad, bv.x);
                fma2(acc2[i][1], ad, bv.y);
            }
        }
        __syncthreads();
    }

    const int col = bcol + tx * 4;
    float4 bb = *(const float4*)&bias[col];
    #pragma unroll
    for (int i = 0; i < 8; i++) {
        int row = brow + ty * 8 + i;
        float4 v;
        unpack2(acc2[i][0], v.x, v.y);
        unpack2(acc2[i][1], v.z, v.w);
        v.x += bb.x; v.y += bb.y; v.z += bb.z; v.w += bb.w;
        if (doRelu) {
            v.x = fmaxf(v.x, 0.0f); v.y = fmaxf(v.y, 0.0f);
            v.z = fmaxf(v.z, 0.0f); v.w = fmaxf(v.w, 0.0f);
        }
        *(float4*)&C[(size_t)row * N + col] = v;
    }
}

// ---------------------------------------------------------------------------
// G = A A^T (64x64), then Gauss-Jordan inverse (well-conditioned Wishart).
// ---------------------------------------------------------------------------
__global__ __launch_bounds__(256) void aat_inv_kernel(const float* __restrict__ A)
{
    __shared__ float Wk[M_CON][2 * M_CON];
    __shared__ float fcol[M_CON];
    const int tid = threadIdx.x;

    for (int idx = tid; idx < M_CON * M_CON; idx += 256) {
        int r = idx >> 6, c = idx & 63;
        float s = 0.0f;
        for (int d = 0; d < D_DIM; d++)
            s = fmaf(A[r * D_DIM + d], A[c * D_DIM + d], s);
        Wk[r][c] = s;
        Wk[r][M_CON + c] = (r == c) ? 1.0f : 0.0f;
    }
    __syncthreads();

    for (int k = 0; k < M_CON; k++) {
        if (tid < M_CON) fcol[tid] = Wk[tid][k];
        __syncthreads();
        float pivinv = 1.0f / fcol[k];
        if (tid < 2 * M_CON) Wk[k][tid] *= pivinv;
        __syncthreads();
        for (int idx = tid; idx < M_CON * 2 * M_CON; idx += 256) {
            int r = idx >> 7, c = idx & 127;
            if (r != k) Wk[r][c] = fmaf(-fcol[r], Wk[k][c], Wk[r][c]);
        }
        __syncthreads();
    }

    for (int idx = tid; idx < M_CON * M_CON; idx += 256) {
        int r = idx >> 6, c = idx & 63;
        g_Ginv[idx] = Wk[r][M_CON + c];
    }
}

// MopNeg[m][d] = -sum_j Ginv[m][j] * A[j][d]   (negated so iterate can FMA-add)
__global__ __launch_bounds__(256) void mop_kernel(const float* __restrict__ A)
{
    int m = blockIdx.x, d = threadIdx.x;
    float s = 0.0f;
    #pragma unroll 8
    for (int j = 0; j < M_CON; j++)
        s = fmaf(g_Ginv[m * M_CON + j], A[j * D_DIM + d], s);
    g_MopNeg[m * D_DIM + d] = -s;
}

// ---------------------------------------------------------------------------
// Persistent DR iteration kernel, FFMA2-packed over row pairs, 512 threads.
// Thread mapping:
//   phases 1/3/4: (d = tid & 255, half = tid >> 8) -> owns pairs
//                 p = half*8 + q (q=0..7), i.e. 16 of the 32 rows at column d.
//   phase 2     : (mi = tid & 63, g = tid >> 6)    -> pairs j in {2g, 2g+1}.
// Shared layouts (row-pair-interleaved so packed operands are 64-bit LDS):
//   tS2[p][d]  : float2 {t[2p][d],  t[2p+1][d]}
//   sS2[p][m]  : float2 {s[2p][m],  s[2p+1][m]}
//   bc2[p][m]  : float2 {-bc[2p][m],-bc[2p+1][m]}
// ---------------------------------------------------------------------------
#define SAT_OFF 0                          // sAT[d][m]  : 256*64
#define SMOP_OFF (SAT_OFF + 256 * 64)      // sM[m][d]   : 64*256 (pre-negated)
#define TS_OFF  (SMOP_OFF + 64 * 256)      // tS2        : 16*256*2
#define SS_OFF  (TS_OFF + 16 * 256 * 2)    // sS2        : 16*64*2
#define BC_OFF  (SS_OFF + 16 * 64 * 2)     // bc2        : 16*64*2
#define ITER_SMEM_FLOATS (BC_OFF + 16 * 64 * 2)
#define ITER_SMEM_BYTES (ITER_SMEM_FLOATS * 4)

__global__ __launch_bounds__(ITHREADS, 1) void iterate_kernel(
    const float* __restrict__ bcon, const float* __restrict__ A,
    const float* __restrict__ y0g, float* __restrict__ out)
{
    extern __shared__ float sm[];
    float* sAT = sm + SAT_OFF;
    float* sM  = sm + SMOP_OFF;
    float* tS2 = sm + TS_OFF;
    float* sS2 = sm + SS_OFF;
    float* bc2 = sm + BC_OFF;

    const int tid  = threadIdx.x;
    const int row0 = blockIdx.x * TR;

    // stage operands
    for (int i = tid; i < M_CON * D_DIM; i += ITHREADS) {
        int m = i >> 8, d = i & 255;               // A is [64][256] row-major
        sAT[d * M_CON + m] = A[i];
    }
    for (int i = tid; i < M_CON * D_DIM; i += ITHREADS) sM[i] = g_MopNeg[i];
    for (int i = tid; i < TR * M_CON; i += ITHREADS) {
        int r = i >> 6, m = i & 63;
        int p = r >> 1, h = r & 1;
        bc2[(p * M_CON + m) * 2 + h] = -bcon[(size_t)(row0 + r) * M_CON + m];
    }

    const int d    = tid & 255;      // owned column
    const int half = tid >> 8;       // 0 or 1: pairs half*8 .. half*8+7
    const int pbase = half * 8;

    // local state: 16 rows (8 pairs) at column d
    float z[16], y0r[16];
    #pragma unroll
    for (int q = 0; q < 8; q++) {
        int p = pbase + q;
        y0r[2 * q]     = y0g[(size_t)(row0 + 2 * p)     * D_DIM + d];
        y0r[2 * q + 1] = y0g[(size_t)(row0 + 2 * p + 1) * D_DIM + d];
        z[2 * q]     = y0r[2 * q];
        z[2 * q + 1] = y0r[2 * q + 1];
    }
    __syncthreads();

    const int mi = tid & 63;     // constraint index (phase 2)
    const int pg = tid >> 6;     // pair-group: pairs 2*pg, 2*pg+1

    unsigned long long acc2[8];  // packed row-pair accumulators (t / y)

    #pragma unroll 1
    for (int it = 0; it < N_ITER; it++) {
        // ---- phase 1: t = (z + y0) * 0.5 ; pack pairs, keep in regs + smem ----
        #pragma unroll
        for (int q = 0; q < 8; q++) {
            float t0 = (z[2 * q]     + y0r[2 * q])     * 0.5f;
            float t1 = (z[2 * q + 1] + y0r[2 * q + 1]) * 0.5f;
            unsigned long long tp = pack2(t0, t1);
            acc2[q] = tp;
            *(unsigned long long*)&tS2[((pbase + q) * D_DIM + d) * 2] = tp;
        }
        __syncthreads();

        // ---- phase 2: s[pair][mi] = t[pair] . A[mi] - bc[pair][mi] (packed) ----
        {
            unsigned long long a2[2];
            a2[0] = *(const unsigned long long*)&bc2[((2 * pg)     * M_CON + mi) * 2];
            a2[1] = *(const unsigned long long*)&bc2[((2 * pg + 1) * M_CON + mi) * 2];
            #pragma unroll 4
            for (int dd = 0; dd < D_DIM; dd += 4) {
                unsigned long long w0 = dup2(sAT[(dd + 0) * M_CON + mi]);
                unsigned long long w1 = dup2(sAT[(dd + 1) * M_CON + mi]);
                unsigned long long w2 = dup2(sAT[(dd + 2) * M_CON + mi]);
                unsigned long long w3 = dup2(sAT[(dd + 3) * M_CON + mi]);
                #pragma unroll
                for (int j = 0; j < 2; j++) {
                    const ulonglong2* tp =
                        (const ulonglong2*)&tS2[((2 * pg + j) * D_DIM + dd) * 2];
                    ulonglong2 vA = tp[0];   // pairs for dd, dd+1
                    ulonglong2 vB = tp[1];   // pairs for dd+2, dd+3
                    fma2(a2[j], vA.x, w0);
                    fma2(a2[j], vA.y, w1);
                    fma2(a2[j], vB.x, w2);
                    fma2(a2[j], vB.y, w3);
                }
            }
            *(unsigned long long*)&sS2[((2 * pg)     * M_CON + mi) * 2] = a2[0];
            *(unsigned long long*)&sS2[((2 * pg + 1) * M_CON + mi) * 2] = a2[1];
        }
        __syncthreads();

        // ---- phase 3: y[pair][d] = t[pair][d] + sum_m s[pair][m]*MopNeg[m][d] ----
        #pragma unroll 2
        for (int m = 0; m < M_CON; m += 4) {
            unsigned long long q0 = dup2(sM[(m + 0) * D_DIM + d]);
            unsigned long long q1 = dup2(sM[(m + 1) * D_DIM + d]);
            unsigned long long q2 = dup2(sM[(m + 2) * D_DIM + d]);
            unsigned long long q3 = dup2(sM[(m + 3) * D_DIM + d]);
            #pragma unroll
            for (int q = 0; q < 8; q++) {
                const ulonglong2* sp =
                    (const ulonglong2*)&sS2[((pbase + q) * M_CON + m) * 2];
                ulonglong2 sA = sp[0];   // pairs for m, m+1
                ulonglong2 sB = sp[1];   // pairs for m+2, m+3
                fma2(acc2[q], sA.x, q0);
                fma2(acc2[q], sA.y, q1);
                fma2(acc2[q], sB.x, q2);
                fma2(acc2[q], sB.y, q3);
            }
        }

        // ---- phase 4: w = max(2y - z, 0);  z += omega * (w - y) ----
        #pragma unroll
        for (int q = 0; q < 8; q++) {
            float ya, yb;
            unpack2(acc2[q], ya, yb);
            float wa = fmaxf(2.0f * ya - z[2 * q],     0.0f);
            float wb = fmaxf(2.0f * yb - z[2 * q + 1], 0.0f);
            z[2 * q]     = fmaf(1.7f, wa - ya, z[2 * q]);
            z[2 * q + 1] = fmaf(1.7f, wb - yb, z[2 * q + 1]);
        }
    }

    #pragma unroll
    for (int q = 0; q < 8; q++) {
        int p = pbase + q;
        float ya, yb;
        unpack2(acc2[q], ya, yb);
        out[(size_t)(row0 + 2 * p)     * D_DIM + d] = ya;
        out[(size_t)(row0 + 2 * p + 1) * D_DIM + d] = yb;
    }
}

// ---------------------------------------------------------------------------
extern "C" void kernel_launch(void* const* d_in, const int* in_sizes, int n_in,
                              void* d_out, int out_size)
{
    const float* x    = (const float*)d_in[0];
    const float* bcon = (const float*)d_in[1];
    const float* A    = (const float*)d_in[2];
    const float* W1   = (const float*)d_in[3];
    const float* b1   = (const float*)d_in[4];
    const float* W2   = (const float*)d_in[5];
    const float* b2   = (const float*)d_in[6];
    const float* W3   = (const float*)d_in[7];
    const float* b3   = (const float*)d_in[8];
    const float* Wout = (const float*)d_in[9];
    const float* bout = (const float*)d_in[10];
    float* out = (float*)d_out;

    float *h1, *h2, *y0;
    cudaGetSymbolAddress((void**)&h1, g_h1);
    cudaGetSymbolAddress((void**)&h2, g_h2);
    cudaGetSymbolAddress((void**)&y0, g_y0);

    cudaFuncSetAttribute(iterate_kernel,
                         cudaFuncAttributeMaxDynamicSharedMemorySize,
                         ITER_SMEM_BYTES);

    dim3 blk(256);
    // MLP trunk (BM=128, BN=64 tiles -> 256/256/256/128-block grids)
    gemm_bias_act<<<dim3(H_DIM / 64, B_ROWS / 128), blk>>>(x,  W1, b1, h1, B_ROWS, H_DIM, DIM_IN, 1);
    gemm_bias_act<<<dim3(H_DIM / 64, B_ROWS / 128), blk>>>(h1, W2, b2, h2, B_ROWS, H_DIM, H_DIM, 1);
    gemm_bias_act<<<dim3(H_DIM / 64, B_ROWS / 128), blk>>>(h2, W3, b3, h1, B_ROWS, H_DIM, H_DIM, 1);
    gemm_bias_act<<<dim3(D_DIM / 64, B_ROWS / 128), blk>>>(h1, Wout, bout, y0, B_ROWS, D_DIM, H_DIM, 0);

    // projection operator setup
    aat_inv_kernel<<<1, 256>>>(A);
    mop_kernel<<<M_CON, D_DIM>>>(A);

    // 100 Douglas-Rachford iterations, persistent (512 threads/block)
    iterate_kernel<<<B_ROWS / TR, ITHREADS, ITER_SMEM_BYTES>>>(bcon, A, y0, out);
}

// round 12
// speedup vs baseline: 1.5271x; 1.5271x over previous
#include <cuda_runtime.h>
#include <cuda_fp16.h>
#include <cstdint>

// Problem constants (fixed by the dataset)
#define B_ROWS 4096
#define DIM_IN 128
#define H_DIM  512
#define D_DIM  256
#define M_CON  64
#define N_ITER 100

// Scratch (device globals: no allocation allowed)
__device__ float g_h1[B_ROWS * H_DIM];
__device__ float g_h2[B_ROWS * H_DIM];
__device__ float g_y0[B_ROWS * D_DIM];
__device__ float g_MopNeg[M_CON * D_DIM];   // -K A (pre-negated)

// ===========================================================================
// Warp MMA helpers (sm_75+ baseline: work on plain sm_103 target)
// ===========================================================================
__device__ __forceinline__ uint32_t smem_to_u32(const void* p) {
    uint32_t a;
    asm("{ .reg .u64 t; cvta.to.shared.u64 t, %1; cvt.u32.u64 %0, t; }"
        : "=r"(a) : "l"(p));
    return a;
}
__device__ __forceinline__ void ldsm4(uint32_t* r, uint32_t addr) {
    asm volatile("ldmatrix.sync.aligned.m8n8.x4.shared.b16 {%0,%1,%2,%3}, [%4];"
                 : "=r"(r[0]), "=r"(r[1]), "=r"(r[2]), "=r"(r[3]) : "r"(addr));
}
__device__ __forceinline__ void mma16816(float* c, const uint32_t* a,
                                         uint32_t b0, uint32_t b1) {
    asm volatile("mma.sync.aligned.m16n8k16.row.col.f32.f16.f16.f32 "
                 "{%0,%1,%2,%3}, {%4,%5,%6,%7}, {%8,%9}, {%0,%1,%2,%3};"
                 : "+f"(c[0]), "+f"(c[1]), "+f"(c[2]), "+f"(c[3])
                 : "r"(a[0]), "r"(a[1]), "r"(a[2]), "r"(a[3]), "r"(b0), "r"(b1));
}
__device__ __forceinline__ uint32_t f16x2_rn(float v0, float v1) {
    __half2 h = __floats2half2_rn(v0, v1);   // v0 -> low half
    return *(uint32_t*)&h;
}
__device__ __forceinline__ float2 f16x2_back(uint32_t u) {
    __half2 h = *(__half2*)&u;
    return __half22float2(h);
}

// smem map for the iterate kernel (u32 units). Row strides padded +4 u32 so
// both ldmatrix row-gathers and the fragment STS hit 32 distinct banks.
#define ZB0_OFF 0                          // zb split0: [32 rows][132] (256 f16 + pad)
#define ZB1_OFF (32 * 132)
#define SS0_OFF (2 * 32 * 132)             // s split0: [32 rows][36] (64 f16 + pad)
#define SS1_OFF (SS0_OFF + 32 * 36)
#define AT0_OFF (SS1_OFF + 32 * 36)        // 0.5*A split0: [64 mi][264 f16] = [64][132]
#define AT1_OFF (AT0_OFF + 64 * 132)
#define MT0_OFF (AT1_OFF + 64 * 132)       // MopNegT split0: [256 d][72 f16] = [256][36]
#define MT1_OFF (MT0_OFF + 256 * 36)
#define ITER_SMEM_U32 (MT1_OFF + 256 * 36)
#define ITER_SMEM_BYTES (ITER_SMEM_U32 * 4)   // 184320

// ===========================================================================
// Trunk SGEMM (best-known version): C = act(X @ W + bias)
// ===========================================================================
__device__ __forceinline__ unsigned long long dup2(float v) {
    unsigned long long r;
    asm("mov.b64 %0, {%1, %1};" : "=l"(r) : "f"(v));
    return r;
}
__device__ __forceinline__ void fma2(unsigned long long& d,
                                     unsigned long long a, unsigned long long b) {
    asm("fma.rn.f32x2 %0, %1, %2, %0;" : "+l"(d) : "l"(a), "l"(b));
}
__device__ __forceinline__ void unpack2(unsigned long long v, float& lo, float& hi) {
    asm("mov.b64 {%0, %1}, %2;" : "=f"(lo), "=f"(hi) : "l"(v));
}

__global__ __launch_bounds__(256) void gemm_bias_act(
    const float* __restrict__ X, const float* __restrict__ W,
    const float* __restrict__ bias, float* __restrict__ C,
    int M, int N, int K, int doRelu)
{
    __shared__ float Xs[16][128];
    __shared__ float Ws[16][64];

    const int tid  = threadIdx.x;
    const int brow = blockIdx.y * 128;
    const int bcol = blockIdx.x * 64;
    const int tx   = tid & 15;
    const int ty   = tid >> 4;
    const int xr0 = tid >> 2;
    const int xc0 = (tid & 3) * 4;
    const int wr0 = tid >> 4;
    const int wc0 = (tid & 15) * 4;

    unsigned long long acc2[8][2];
    #pragma unroll
    for (int i = 0; i < 8; i++) { acc2[i][0] = 0ULL; acc2[i][1] = 0ULL; }

    for (int kt = 0; kt < K; kt += 16) {
        float4 xv0 = *(const float4*)&X[(size_t)(brow + xr0) * K + kt + xc0];
        float4 xv1 = *(const float4*)&X[(size_t)(brow + xr0 + 64) * K + kt + xc0];
        float4 wv  = *(const float4*)&W[(size_t)(kt + wr0) * N + bcol + wc0];

        Xs[xc0 + 0][xr0] = xv0.x;  Xs[xc0 + 1][xr0] = xv0.y;
        Xs[xc0 + 2][xr0] = xv0.z;  Xs[xc0 + 3][xr0] = xv0.w;
        Xs[xc0 + 0][xr0 + 64] = xv1.x;  Xs[xc0 + 1][xr0 + 64] = xv1.y;
        Xs[xc0 + 2][xr0 + 64] = xv1.z;  Xs[xc0 + 3][xr0 + 64] = xv1.w;
        *(float4*)&Ws[wr0][wc0] = wv;
        __syncthreads();

        #pragma unroll
        for (int k = 0; k < 16; k++) {
            float a[8];
            float4 a0 = *(const float4*)&Xs[k][ty * 8];
            float4 a1 = *(const float4*)&Xs[k][ty * 8 + 4];
            a[0]=a0.x; a[1]=a0.y; a[2]=a0.z; a[3]=a0.w;
            a[4]=a1.x; a[5]=a1.y; a[6]=a1.z; a[7]=a1.w;
            ulonglong2 bv = *(const ulonglong2*)&Ws[k][tx * 4];
            #pragma unroll
            for (int i = 0; i < 8; i++) {
                unsigned long long ad = dup2(a[i]);
                fma2(acc2[i][0], ad, bv.x);
                fma2(acc2[i][1], ad, bv.y);
            }
        }
        __syncthreads();
    }

    const int col = bcol + tx * 4;
    float4 bb = *(const float4*)&bias[col];
    #pragma unroll
    for (int i = 0; i < 8; i++) {
        int row = brow + ty * 8 + i;
        float4 v;
        unpack2(acc2[i][0], v.x, v.y);
        unpack2(acc2[i][1], v.z, v.w);
        v.x += bb.x; v.y += bb.y; v.z += bb.z; v.w += bb.w;
        if (doRelu) {
            v.x = fmaxf(v.x, 0.0f); v.y = fmaxf(v.y, 0.0f);
            v.z = fmaxf(v.z, 0.0f); v.w = fmaxf(v.w, 0.0f);
        }
        *(float4*)&C[(size_t)row * N + col] = v;
    }
}

// ===========================================================================
// Fused setup (single block): G = A Aᵀ -> Gauss-Jordan inverse -> MopNeg = -K A
// ===========================================================================
__global__ __launch_bounds__(256) void setup_kernel(const float* __restrict__ A)
{
    __shared__ float Wk[M_CON][2 * M_CON];
    __shared__ float fcol[M_CON];
    const int tid = threadIdx.x;

    for (int idx = tid; idx < M_CON * M_CON; idx += 256) {
        int r = idx >> 6, c = idx & 63;
        float s = 0.0f;
        for (int d = 0; d < D_DIM; d++)
            s = fmaf(A[r * D_DIM + d], A[c * D_DIM + d], s);
        Wk[r][c] = s;
        Wk[r][M_CON + c] = (r == c) ? 1.0f : 0.0f;
    }
    __syncthreads();

    for (int k = 0; k < M_CON; k++) {
        if (tid < M_CON) fcol[tid] = Wk[tid][k];
        __syncthreads();
        float pivinv = 1.0f / fcol[k];
        if (tid < 2 * M_CON) Wk[k][tid] *= pivinv;
        __syncthreads();
        for (int idx = tid; idx < M_CON * 2 * M_CON; idx += 256) {
            int r = idx >> 7, c = idx & 127;
            if (r != k) Wk[r][c] = fmaf(-fcol[r], Wk[k][c], Wk[r][c]);
        }
        __syncthreads();
    }

    for (int idx = tid; idx < M_CON * D_DIM; idx += 256) {
        int m = idx >> 8, d = idx & 255;
        float s = 0.0f;
        #pragma unroll 8
        for (int j = 0; j < M_CON; j++)
            s = fmaf(Wk[m][M_CON + j], A[j * D_DIM + d], s);
        g_MopNeg[idx] = -s;
    }
}

// ===========================================================================
// HMMA DR iteration kernel. grid=128, TR=32 rows/block, 256 threads (8 warps).
// warp = (r = wid&1: row half, c = wid>>1: d-quarter). Warp's registers hold
// zb = z+y0, y0, and -bc in m16n8 C-fragment layout; zb and s round-trip
// through padded smem as 2-term fp16 splits for ldmatrix.
// Per iter: ph2 s = zb·(0.5A)ᵀ - bc  (K=256, 3 split products)
//           ph3 Δ = s·MopNegᵀ        (K=64,  3 split products)
//           ph4 y = 0.5 zb + Δ; w = max(2y - zb + y0, 0); zb += 1.7 (w - y)
// ===========================================================================
__global__ __launch_bounds__(256, 1) void iterate_mma(
    const float* __restrict__ bcon, const float* __restrict__ A,
    const float* __restrict__ y0g, float* __restrict__ out)
{
    extern __shared__ uint32_t sm[];
    const uint32_t sb = smem_to_u32(sm);
    const int tid  = threadIdx.x;
    const int lane = tid & 31;
    const int wid  = tid >> 5;
    const int r    = wid & 1;      // row half: rows r*16 .. r*16+15
    const int c    = wid >> 1;     // d quarter: cols c*64 .. c*64+63 (m: c*16..)

    // ---- constant tiles: fp16 2-term splits ----
    for (int i = tid; i < M_CON * D_DIM; i += 256) {
        int mi = i >> 8, d = i & 255;
        float v = 0.5f * A[i];
        __half h0 = __float2half_rn(v);
        __half h1 = __float2half_rn(v - __half2float(h0));
        ((__half*)(sm + AT0_OFF))[mi * 264 + d] = h0;
        ((__half*)(sm + AT1_OFF))[mi * 264 + d] = h1;
    }
    for (int i = tid; i < M_CON * D_DIM; i += 256) {
        int m = i >> 8, d = i & 255;
        float v = g_MopNeg[i];
        __half h0 = __float2half_rn(v);
        __half h1 = __float2half_rn(v - __half2float(h0));
        ((__half*)(sm + MT0_OFF))[d * 72 + m] = h0;
        ((__half*)(sm + MT1_OFF))[d * 72 + m] = h1;
    }

    // ---- fragment geometry ----
    const int g = lane >> 2, t = lane & 3;          // C-frag: rows g,g+8; cols 2t,2t+1
    const int mat = lane >> 3, lrow = lane & 7;     // ldmatrix lane mapping
    const int arow  = ((mat & 1) << 3) + lrow;      // A-op: row_local
    const int akoff = (mat >> 1) << 3;              //       k half (f16 units)
    const int bnrow = ((lane >> 4) << 3) + lrow;    // B-op: n row
    const int bkoff = ((lane >> 3) & 1) << 3;       //       k half

    const uint32_t zb_a0 = sb + 4 * (ZB0_OFF + (r * 16 + arow) * 132 + (akoff >> 1));
    const uint32_t zb_a1 = sb + 4 * (ZB1_OFF + (r * 16 + arow) * 132 + (akoff >> 1));
    const uint32_t at_b0 = sb + 4 * (AT0_OFF + (c * 16 + bnrow) * 132 + (bkoff >> 1));
    const uint32_t at_b1 = sb + 4 * (AT1_OFF + (c * 16 + bnrow) * 132 + (bkoff >> 1));
    const uint32_t ss_a0 = sb + 4 * (SS0_OFF + (r * 16 + arow) * 36 + (akoff >> 1));
    const uint32_t ss_a1 = sb + 4 * (SS1_OFF + (r * 16 + arow) * 36 + (akoff >> 1));
    const uint32_t mt_b0 = sb + 4 * (MT0_OFF + (c * 64 + bnrow) * 36 + (bkoff >> 1));
    const uint32_t mt_b1 = sb + 4 * (MT1_OFF + (c * 64 + bnrow) * 36 + (bkoff >> 1));

    // zb/s STS bases (u32 index): row (r*16+g[+8]) * stride + col/2 + t
    const int zrow0 = (r * 16 + g) * 132 + (c * 64) / 2 + t;
    const int zrow1 = (r * 16 + 8 + g) * 132 + (c * 64) / 2 + t;
    const int srow0 = (r * 16 + g) * 36 + (c * 16) / 2 + t;
    const int srow1 = (r * 16 + 8 + g) * 36 + (c * 16) / 2 + t;

    // ---- state fragments ----
    const int row0 = blockIdx.x * 32 + r * 16;
    const float* y0p0 = y0g + (size_t)(row0 + g) * D_DIM + c * 64;
    const float* y0p1 = y0g + (size_t)(row0 + 8 + g) * D_DIM + c * 64;
    const float* bcp0 = bcon + (size_t)(row0 + g) * M_CON + c * 16;
    const float* bcp1 = bcon + (size_t)(row0 + 8 + g) * M_CON + c * 16;

    float zb[8][4], y0f[8][4], nbcf[2][4];
    #pragma unroll
    for (int j = 0; j < 8; j++) {
        float2 u = *(const float2*)(y0p0 + j * 8 + 2 * t);
        float2 v = *(const float2*)(y0p1 + j * 8 + 2 * t);
        y0f[j][0] = u.x; y0f[j][1] = u.y; y0f[j][2] = v.x; y0f[j][3] = v.y;
        zb[j][0] = 2.0f * u.x; zb[j][1] = 2.0f * u.y;
        zb[j][2] = 2.0f * v.x; zb[j][3] = 2.0f * v.y;
    }
    #pragma unroll
    for (int j = 0; j < 2; j++) {
        float2 u = *(const float2*)(bcp0 + j * 8 + 2 * t);
        float2 v = *(const float2*)(bcp1 + j * 8 + 2 * t);
        nbcf[j][0] = -u.x; nbcf[j][1] = -u.y; nbcf[j][2] = -v.x; nbcf[j][3] = -v.y;
    }
    __syncthreads();   // tiles ready

    // initial zb split -> smem
    #pragma unroll
    for (int j = 0; j < 8; j++) {
        uint32_t h0a = f16x2_rn(zb[j][0], zb[j][1]);
        float2 b0 = f16x2_back(h0a);
        uint32_t h1a = f16x2_rn(zb[j][0] - b0.x, zb[j][1] - b0.y);
        uint32_t h0b = f16x2_rn(zb[j][2], zb[j][3]);
        float2 b1 = f16x2_back(h0b);
        uint32_t h1b = f16x2_rn(zb[j][2] - b1.x, zb[j][3] - b1.y);
        sm[ZB0_OFF + zrow0 + j * 4] = h0a;
        sm[ZB1_OFF + zrow0 + j * 4] = h1a;
        sm[ZB0_OFF + zrow1 + j * 4] = h0b;
        sm[ZB1_OFF + zrow1 + j * 4] = h1b;
    }
    __syncthreads();

    float* outp0 = out + (size_t)(row0 + g) * D_DIM + c * 64;
    float* outp1 = out + (size_t)(row0 + 8 + g) * D_DIM + c * 64;

    #pragma unroll 1
    for (int it = 0; it < N_ITER; it++) {
        // ---- ph2: s = zb·(0.5A)ᵀ - bc ----
        float sacc[2][4];
        #pragma unroll
        for (int j = 0; j < 2; j++)
            #pragma unroll
            for (int k = 0; k < 4; k++) sacc[j][k] = nbcf[j][k];

        #pragma unroll 4
        for (int kk = 0; kk < 16; kk++) {
            uint32_t za[4], zc[4], ba[4], bb2[4];
            ldsm4(za, zb_a0 + kk * 32);
            ldsm4(zc, zb_a1 + kk * 32);
            ldsm4(ba, at_b0 + kk * 32);
            ldsm4(bb2, at_b1 + kk * 32);
            mma16816(sacc[0], za, ba[0], ba[1]);
            mma16816(sacc[1], za, ba[2], ba[3]);
            mma16816(sacc[0], za, bb2[0], bb2[1]);
            mma16816(sacc[1], za, bb2[2], bb2[3]);
            mma16816(sacc[0], zc, ba[0], ba[1]);
            mma16816(sacc[1], zc, ba[2], ba[3]);
        }

        // s split -> smem
        #pragma unroll
        for (int j = 0; j < 2; j++) {
            uint32_t h0a = f16x2_rn(sacc[j][0], sacc[j][1]);
            float2 b0 = f16x2_back(h0a);
            uint32_t h1a = f16x2_rn(sacc[j][0] - b0.x, sacc[j][1] - b0.y);
            uint32_t h0b = f16x2_rn(sacc[j][2], sacc[j][3]);
            float2 b1 = f16x2_back(h0b);
            uint32_t h1b = f16x2_rn(sacc[j][2] - b1.x, sacc[j][3] - b1.y);
            sm[SS0_OFF + srow0 + j * 4] = h0a;
            sm[SS1_OFF + srow0 + j * 4] = h1a;
            sm[SS0_OFF + srow1 + j * 4] = h0b;
            sm[SS1_OFF + srow1 + j * 4] = h1b;
        }
        __syncthreads();

        // ---- ph3: Δ = s·MopNegᵀ ; cache s A-frags ----
        uint32_t s0[4][4], s1[4][4];
        #pragma unroll
        for (int kk = 0; kk < 4; kk++) {
            ldsm4(s0[kk], ss_a0 + kk * 32);
            ldsm4(s1[kk], ss_a1 + kk * 32);
        }

        const int last = (it == N_ITER - 1);
        #pragma unroll 1
        for (int jj = 0; jj < 4; jj++) {
            float yacc[2][4];
            #pragma unroll
            for (int h = 0; h < 2; h++)
                #pragma unroll
                for (int k = 0; k < 4; k++) yacc[h][k] = 0.0f;

            #pragma unroll
            for (int kk = 0; kk < 4; kk++) {
                uint32_t m0[4], m1[4];
                ldsm4(m0, mt_b0 + (uint32_t)(jj * 16 * 36 * 4) + kk * 32);
                ldsm4(m1, mt_b1 + (uint32_t)(jj * 16 * 36 * 4) + kk * 32);
                mma16816(yacc[0], s0[kk], m0[0], m0[1]);
                mma16816(yacc[1], s0[kk], m0[2], m0[3]);
                mma16816(yacc[0], s0[kk], m1[0], m1[1]);
                mma16816(yacc[1], s0[kk], m1[2], m1[3]);
                mma16816(yacc[0], s1[kk], m0[0], m0[1]);
                mma16816(yacc[1], s1[kk], m0[2], m0[3]);
            }

            // ---- ph4 for ntiles j = 2jj, 2jj+1 ----
            #pragma unroll
            for (int h = 0; h < 2; h++) {
                const int j = 2 * jj + h;
                float yv[4];
                #pragma unroll
                for (int k = 0; k < 4; k++) {
                    float zv = zb[j][k];
                    float y = fmaf(0.5f, zv, yacc[h][k]);
                    float w = fmaxf(2.0f * y - zv + y0f[j][k], 0.0f);
                    zb[j][k] = fmaf(1.7f, w - y, zv);
                    yv[k] = y;
                }
                // re-split new zb -> smem
                uint32_t h0a = f16x2_rn(zb[j][0], zb[j][1]);
                float2 b0 = f16x2_back(h0a);
                uint32_t h1a = f16x2_rn(zb[j][0] - b0.x, zb[j][1] - b0.y);
                uint32_t h0b = f16x2_rn(zb[j][2], zb[j][3]);
                float2 b1 = f16x2_back(h0b);
                uint32_t h1b = f16x2_rn(zb[j][2] - b1.x, zb[j][3] - b1.y);
                sm[ZB0_OFF + zrow0 + j * 4] = h0a;
                sm[ZB1_OFF + zrow0 + j * 4] = h1a;
                sm[ZB0_OFF + zrow1 + j * 4] = h0b;
                sm[ZB1_OFF + zrow1 + j * 4] = h1b;
                if (last) {
                    *(float2*)(outp0 + j * 8 + 2 * t) = make_float2(yv[0], yv[1]);
                    *(float2*)(outp1 + j * 8 + 2 * t) = make_float2(yv[2], yv[3]);
                }
            }
        }
        __syncthreads();
    }
}

// ---------------------------------------------------------------------------
extern "C" void kernel_launch(void* const* d_in, const int* in_sizes, int n_in,
                              void* d_out, int out_size)
{
    const float* x    = (const float*)d_in[0];
    const float* bcon = (const float*)d_in[1];
    const float* A    = (const float*)d_in[2];
    const float* W1   = (const float*)d_in[3];
    const float* b1   = (const float*)d_in[4];
    const float* W2   = (const float*)d_in[5];
    const float* b2   = (const float*)d_in[6];
    const float* W3   = (const float*)d_in[7];
    const float* b3   = (const float*)d_in[8];
    const float* Wout = (const float*)d_in[9];
    const float* bout = (const float*)d_in[10];
    float* out = (float*)d_out;

    float *h1, *h2, *y0;
    cudaGetSymbolAddress((void**)&h1, g_h1);
    cudaGetSymbolAddress((void**)&h2, g_h2);
    cudaGetSymbolAddress((void**)&y0, g_y0);

    cudaFuncSetAttribute(iterate_mma,
                         cudaFuncAttributeMaxDynamicSharedMemorySize,
                         ITER_SMEM_BYTES);

    dim3 blk(256);
    // MLP trunk
    gemm_bias_act<<<dim3(H_DIM / 64, B_ROWS / 128), blk>>>(x,  W1, b1, h1, B_ROWS, H_DIM, DIM_IN, 1);
    gemm_bias_act<<<dim3(H_DIM / 64, B_ROWS / 128), blk>>>(h1, W2, b2, h2, B_ROWS, H_DIM, H_DIM, 1);
    gemm_bias_act<<<dim3(H_DIM / 64, B_ROWS / 128), blk>>>(h2, W3, b3, h1, B_ROWS, H_DIM, H_DIM, 1);
    gemm_bias_act<<<dim3(D_DIM / 64, B_ROWS / 128), blk>>>(h1, Wout, bout, y0, B_ROWS, D_DIM, H_DIM, 0);

    // projection operator setup (fused)
    setup_kernel<<<1, 256>>>(A);

    // 100 Douglas-Rachford iterations on tensor cores (mma.sync)
    iterate_mma<<<B_ROWS / 32, 256, ITER_SMEM_BYTES>>>(bcon, A, y0, out);
}

// round 13
// speedup vs baseline: 1.5422x; 1.0099x over previous
#include <cuda_runtime.h>
#include <cuda_fp16.h>
#include <cstdint>

// Problem constants (fixed by the dataset)
#define B_ROWS 4096
#define DIM_IN 128
#define H_DIM  512
#define D_DIM  256
#define M_CON  64
#define N_ITER 100

// Scratch (device globals: no allocation allowed)
__device__ float g_h1[B_ROWS * H_DIM];
__device__ float g_h2[B_ROWS * H_DIM];
__device__ float g_y0[B_ROWS * D_DIM];
__device__ float g_MopNeg[M_CON * D_DIM];   // -K A (pre-negated)

// ===========================================================================
// Warp MMA helpers (sm_75+ baseline: work on plain sm_103 target)
// ===========================================================================
__device__ __forceinline__ uint32_t smem_to_u32(const void* p) {
    uint32_t a;
    asm("{ .reg .u64 t; cvta.to.shared.u64 t, %1; cvt.u32.u64 %0, t; }"
        : "=r"(a) : "l"(p));
    return a;
}
__device__ __forceinline__ void ldsm4(uint32_t* r, uint32_t addr) {
    asm volatile("ldmatrix.sync.aligned.m8n8.x4.shared.b16 {%0,%1,%2,%3}, [%4];"
                 : "=r"(r[0]), "=r"(r[1]), "=r"(r[2]), "=r"(r[3]) : "r"(addr));
}
__device__ __forceinline__ void mma16816(float* c, const uint32_t* a,
                                         uint32_t b0, uint32_t b1) {
    asm volatile("mma.sync.aligned.m16n8k16.row.col.f32.f16.f16.f32 "
                 "{%0,%1,%2,%3}, {%4,%5,%6,%7}, {%8,%9}, {%0,%1,%2,%3};"
                 : "+f"(c[0]), "+f"(c[1]), "+f"(c[2]), "+f"(c[3])
                 : "r"(a[0]), "r"(a[1]), "r"(a[2]), "r"(a[3]), "r"(b0), "r"(b1));
}
__device__ __forceinline__ uint32_t f16x2_rn(float v0, float v1) {
    __half2 h = __floats2half2_rn(v0, v1);   // v0 -> low half
    return *(uint32_t*)&h;
}
__device__ __forceinline__ float2 f16x2_back(uint32_t u) {
    __half2 h = *(__half2*)&u;
    return __half22float2(h);
}

// smem map for the iterate kernel (u32 units). Row strides padded +4 u32 so
// both ldmatrix row-gathers and the fragment STS hit 32 distinct banks.
#define ZB0_OFF 0                          // zb split0: [32 rows][132] (256 f16 + pad)
#define ZB1_OFF (32 * 132)
#define SS0_OFF (2 * 32 * 132)             // s split0: [32 rows][36] (64 f16 + pad)
#define SS1_OFF (SS0_OFF + 32 * 36)
#define AT0_OFF (SS1_OFF + 32 * 36)        // 0.5*A split0: [64 mi][264 f16] = [64][132]
#define AT1_OFF (AT0_OFF + 64 * 132)
#define MT0_OFF (AT1_OFF + 64 * 132)       // MopNegT split0: [256 d][72 f16] = [256][36]
#define MT1_OFF (MT0_OFF + 256 * 36)
#define ITER_SMEM_U32 (MT1_OFF + 256 * 36)
#define ITER_SMEM_BYTES (ITER_SMEM_U32 * 4)   // 184320

// ===========================================================================
// Trunk SGEMM (best-known version): C = act(X @ W + bias)
// ===========================================================================
__device__ __forceinline__ unsigned long long dup2(float v) {
    unsigned long long r;
    asm("mov.b64 %0, {%1, %1};" : "=l"(r) : "f"(v));
    return r;
}
__device__ __forceinline__ void fma2(unsigned long long& d,
                                     unsigned long long a, unsigned long long b) {
    asm("fma.rn.f32x2 %0, %1, %2, %0;" : "+l"(d) : "l"(a), "l"(b));
}
__device__ __forceinline__ void unpack2(unsigned long long v, float& lo, float& hi) {
    asm("mov.b64 {%0, %1}, %2;" : "=f"(lo), "=f"(hi) : "l"(v));
}

__global__ __launch_bounds__(256) void gemm_bias_act(
    const float* __restrict__ X, const float* __restrict__ W,
    const float* __restrict__ bias, float* __restrict__ C,
    int M, int N, int K, int doRelu)
{
    __shared__ float Xs[16][128];
    __shared__ float Ws[16][64];

    const int tid  = threadIdx.x;
    const int brow = blockIdx.y * 128;
    const int bcol = blockIdx.x * 64;
    const int tx   = tid & 15;
    const int ty   = tid >> 4;
    const int xr0 = tid >> 2;
    const int xc0 = (tid & 3) * 4;
    const int wr0 = tid >> 4;
    const int wc0 = (tid & 15) * 4;

    unsigned long long acc2[8][2];
    #pragma unroll
    for (int i = 0; i < 8; i++) { acc2[i][0] = 0ULL; acc2[i][1] = 0ULL; }

    for (int kt = 0; kt < K; kt += 16) {
        float4 xv0 = *(const float4*)&X[(size_t)(brow + xr0) * K + kt + xc0];
        float4 xv1 = *(const float4*)&X[(size_t)(brow + xr0 + 64) * K + kt + xc0];
        float4 wv  = *(const float4*)&W[(size_t)(kt + wr0) * N + bcol + wc0];

        Xs[xc0 + 0][xr0] = xv0.x;  Xs[xc0 + 1][xr0] = xv0.y;
        Xs[xc0 + 2][xr0] = xv0.z;  Xs[xc0 + 3][xr0] = xv0.w;
        Xs[xc0 + 0][xr0 + 64] = xv1.x;  Xs[xc0 + 1][xr0 + 64] = xv1.y;
        Xs[xc0 + 2][xr0 + 64] = xv1.z;  Xs[xc0 + 3][xr0 + 64] = xv1.w;
        *(float4*)&Ws[wr0][wc0] = wv;
        __syncthreads();

        #pragma unroll
        for (int k = 0; k < 16; k++) {
            float a[8];
            float4 a0 = *(const float4*)&Xs[k][ty * 8];
            float4 a1 = *(const float4*)&Xs[k][ty * 8 + 4];
            a[0]=a0.x; a[1]=a0.y; a[2]=a0.z; a[3]=a0.w;
            a[4]=a1.x; a[5]=a1.y; a[6]=a1.z; a[7]=a1.w;
            ulonglong2 bv = *(const ulonglong2*)&Ws[k][tx * 4];
            #pragma unroll
            for (int i = 0; i < 8; i++) {
                unsigned long long ad = dup2(a[i]);
                fma2(acc2[i][0], ad, bv.x);
                fma2(acc2[i][1], ad, bv.y);
            }
        }
        __syncthreads();
    }

    const int col = bcol + tx * 4;
    float4 bb = *(const float4*)&bias[col];
    #pragma unroll
    for (int i = 0; i < 8; i++) {
        int row = brow + ty * 8 + i;
        float4 v;
        unpack2(acc2[i][0], v.x, v.y);
        unpack2(acc2[i][1], v.z, v.w);
        v.x += bb.x; v.y += bb.y; v.z += bb.z; v.w += bb.w;
        if (doRelu) {
            v.x = fmaxf(v.x, 0.0f); v.y = fmaxf(v.y, 0.0f);
            v.z = fmaxf(v.z, 0.0f); v.w = fmaxf(v.w, 0.0f);
        }
        *(float4*)&C[(size_t)row * N + col] = v;
    }
}

// ===========================================================================
// Fused setup (single block): G = A Aᵀ -> Gauss-Jordan inverse -> MopNeg = -K A
// ===========================================================================
__global__ __launch_bounds__(256) void setup_kernel(const float* __restrict__ A)
{
    __shared__ float Wk[M_CON][2 * M_CON];
    __shared__ float fcol[M_CON];
    const int tid = threadIdx.x;

    for (int idx = tid; idx < M_CON * M_CON; idx += 256) {
        int r = idx >> 6, c = idx & 63;
        float s = 0.0f;
        for (int d = 0; d < D_DIM; d++)
            s = fmaf(A[r * D_DIM + d], A[c * D_DIM + d], s);
        Wk[r][c] = s;
        Wk[r][M_CON + c] = (r == c) ? 1.0f : 0.0f;
    }
    __syncthreads();

    for (int k = 0; k < M_CON; k++) {
        if (tid < M_CON) fcol[tid] = Wk[tid][k];
        __syncthreads();
        float pivinv = 1.0f / fcol[k];
        if (tid < 2 * M_CON) Wk[k][tid] *= pivinv;
        __syncthreads();
        for (int idx = tid; idx < M_CON * 2 * M_CON; idx += 256) {
            int r = idx >> 7, c = idx & 127;
            if (r != k) Wk[r][c] = fmaf(-fcol[r], Wk[k][c], Wk[r][c]);
        }
        __syncthreads();
    }

    for (int idx = tid; idx < M_CON * D_DIM; idx += 256) {
        int m = idx >> 8, d = idx & 255;
        float s = 0.0f;
        #pragma unroll 8
        for (int j = 0; j < M_CON; j++)
            s = fmaf(Wk[m][M_CON + j], A[j * D_DIM + d], s);
        g_MopNeg[idx] = -s;
    }
}

// ===========================================================================
// HMMA DR iteration kernel. grid=128, TR=32 rows/block, 256 threads (8 warps).
// warp = (r = wid&1: row half, c = wid>>1: d-quarter). Registers hold zb, y0,
// -bc in m16n8 C-fragment layout; zb and s round-trip through padded smem as
// 2-term fp16 splits. ILP fix (R12): separate accumulators per split term so
// every k-step issues 6 MMAs into 6 distinct C-fragments (reuse distance 6).
// ===========================================================================
__global__ __launch_bounds__(256, 1) void iterate_mma(
    const float* __restrict__ bcon, const float* __restrict__ A,
    const float* __restrict__ y0g, float* __restrict__ out)
{
    extern __shared__ uint32_t sm[];
    const uint32_t sb = smem_to_u32(sm);
    const int tid  = threadIdx.x;
    const int lane = tid & 31;
    const int wid  = tid >> 5;
    const int r    = wid & 1;      // row half: rows r*16 .. r*16+15
    const int c    = wid >> 1;     // d quarter: cols c*64 .. c*64+63 (m: c*16..)

    // ---- constant tiles: fp16 2-term splits ----
    for (int i = tid; i < M_CON * D_DIM; i += 256) {
        int mi = i >> 8, d = i & 255;
        float v = 0.5f * A[i];
        __half h0 = __float2half_rn(v);
        __half h1 = __float2half_rn(v - __half2float(h0));
        ((__half*)(sm + AT0_OFF))[mi * 264 + d] = h0;
        ((__half*)(sm + AT1_OFF))[mi * 264 + d] = h1;
    }
    for (int i = tid; i < M_CON * D_DIM; i += 256) {
        int m = i >> 8, d = i & 255;
        float v = g_MopNeg[i];
        __half h0 = __float2half_rn(v);
        __half h1 = __float2half_rn(v - __half2float(h0));
        ((__half*)(sm + MT0_OFF))[d * 72 + m] = h0;
        ((__half*)(sm + MT1_OFF))[d * 72 + m] = h1;
    }

    // ---- fragment geometry ----
    const int g = lane >> 2, t = lane & 3;          // C-frag: rows g,g+8; cols 2t,2t+1
    const int mat = lane >> 3, lrow = lane & 7;     // ldmatrix lane mapping
    const int arow  = ((mat & 1) << 3) + lrow;      // A-op: row_local
    const int akoff = (mat >> 1) << 3;              //       k half (f16 units)
    const int bnrow = ((lane >> 4) << 3) + lrow;    // B-op: n row
    const int bkoff = ((lane >> 3) & 1) << 3;       //       k half

    const uint32_t zb_a0 = sb + 4 * (ZB0_OFF + (r * 16 + arow) * 132 + (akoff >> 1));
    const uint32_t zb_a1 = sb + 4 * (ZB1_OFF + (r * 16 + arow) * 132 + (akoff >> 1));
    const uint32_t at_b0 = sb + 4 * (AT0_OFF + (c * 16 + bnrow) * 132 + (bkoff >> 1));
    const uint32_t at_b1 = sb + 4 * (AT1_OFF + (c * 16 + bnrow) * 132 + (bkoff >> 1));
    const uint32_t ss_a0 = sb + 4 * (SS0_OFF + (r * 16 + arow) * 36 + (akoff >> 1));
    const uint32_t ss_a1 = sb + 4 * (SS1_OFF + (r * 16 + arow) * 36 + (akoff >> 1));
    const uint32_t mt_b0 = sb + 4 * (MT0_OFF + (c * 64 + bnrow) * 36 + (bkoff >> 1));
    const uint32_t mt_b1 = sb + 4 * (MT1_OFF + (c * 64 + bnrow) * 36 + (bkoff >> 1));

    // zb/s STS bases (u32 index): row (r*16+g[+8]) * stride + col/2 + t
    const int zrow0 = (r * 16 + g) * 132 + (c * 64) / 2 + t;
    const int zrow1 = (r * 16 + 8 + g) * 132 + (c * 64) / 2 + t;
    const int srow0 = (r * 16 + g) * 36 + (c * 16) / 2 + t;
    const int srow1 = (r * 16 + 8 + g) * 36 + (c * 16) / 2 + t;

    // ---- state fragments ----
    const int row0 = blockIdx.x * 32 + r * 16;
    const float* y0p0 = y0g + (size_t)(row0 + g) * D_DIM + c * 64;
    const float* y0p1 = y0g + (size_t)(row0 + 8 + g) * D_DIM + c * 64;
    const float* bcp0 = bcon + (size_t)(row0 + g) * M_CON + c * 16;
    const float* bcp1 = bcon + (size_t)(row0 + 8 + g) * M_CON + c * 16;

    float zb[8][4], y0f[8][4], nbcf[2][4];
    #pragma unroll
    for (int j = 0; j < 8; j++) {
        float2 u = *(const float2*)(y0p0 + j * 8 + 2 * t);
        float2 v = *(const float2*)(y0p1 + j * 8 + 2 * t);
        y0f[j][0] = u.x; y0f[j][1] = u.y; y0f[j][2] = v.x; y0f[j][3] = v.y;
        zb[j][0] = 2.0f * u.x; zb[j][1] = 2.0f * u.y;
        zb[j][2] = 2.0f * v.x; zb[j][3] = 2.0f * v.y;
    }
    #pragma unroll
    for (int j = 0; j < 2; j++) {
        float2 u = *(const float2*)(bcp0 + j * 8 + 2 * t);
        float2 v = *(const float2*)(bcp1 + j * 8 + 2 * t);
        nbcf[j][0] = -u.x; nbcf[j][1] = -u.y; nbcf[j][2] = -v.x; nbcf[j][3] = -v.y;
    }
    __syncthreads();   // tiles ready

    // initial zb split -> smem
    #pragma unroll
    for (int j = 0; j < 8; j++) {
        uint32_t h0a = f16x2_rn(zb[j][0], zb[j][1]);
        float2 b0 = f16x2_back(h0a);
        uint32_t h1a = f16x2_rn(zb[j][0] - b0.x, zb[j][1] - b0.y);
        uint32_t h0b = f16x2_rn(zb[j][2], zb[j][3]);
        float2 b1 = f16x2_back(h0b);
        uint32_t h1b = f16x2_rn(zb[j][2] - b1.x, zb[j][3] - b1.y);
        sm[ZB0_OFF + zrow0 + j * 4] = h0a;
        sm[ZB1_OFF + zrow0 + j * 4] = h1a;
        sm[ZB0_OFF + zrow1 + j * 4] = h0b;
        sm[ZB1_OFF + zrow1 + j * 4] = h1b;
    }
    __syncthreads();

    float* outp0 = out + (size_t)(row0 + g) * D_DIM + c * 64;
    float* outp1 = out + (size_t)(row0 + 8 + g) * D_DIM + c * 64;

    #pragma unroll 1
    for (int it = 0; it < N_ITER; it++) {
        // ---- ph2: s = zb·(0.5A)ᵀ - bc.  3 term-accumulator sets: each kk
        // issues 6 MMAs into 6 distinct C-frags (dependency distance 6). ----
        float t1[2][4], t2[2][4], t3[2][4];
        #pragma unroll
        for (int j = 0; j < 2; j++)
            #pragma unroll
            for (int k = 0; k < 4; k++) {
                t1[j][k] = nbcf[j][k]; t2[j][k] = 0.0f; t3[j][k] = 0.0f;
            }

        #pragma unroll 4
        for (int kk = 0; kk < 16; kk++) {
            uint32_t za[4], zc[4], ba[4], bb2[4];
            ldsm4(za, zb_a0 + kk * 32);
            ldsm4(zc, zb_a1 + kk * 32);
            ldsm4(ba, at_b0 + kk * 32);
            ldsm4(bb2, at_b1 + kk * 32);
            mma16816(t1[0], za, ba[0], ba[1]);
            mma16816(t1[1], za, ba[2], ba[3]);
            mma16816(t2[0], za, bb2[0], bb2[1]);
            mma16816(t2[1], za, bb2[2], bb2[3]);
            mma16816(t3[0], zc, ba[0], ba[1]);
            mma16816(t3[1], zc, ba[2], ba[3]);
        }

        // merge terms + s split -> smem
        #pragma unroll
        for (int j = 0; j < 2; j++) {
            float v0 = t1[j][0] + t2[j][0] + t3[j][0];
            float v1 = t1[j][1] + t2[j][1] + t3[j][1];
            float v2 = t1[j][2] + t2[j][2] + t3[j][2];
            float v3 = t1[j][3] + t2[j][3] + t3[j][3];
            uint32_t h0a = f16x2_rn(v0, v1);
            float2 b0 = f16x2_back(h0a);
            uint32_t h1a = f16x2_rn(v0 - b0.x, v1 - b0.y);
            uint32_t h0b = f16x2_rn(v2, v3);
            float2 b1 = f16x2_back(h0b);
            uint32_t h1b = f16x2_rn(v2 - b1.x, v3 - b1.y);
            sm[SS0_OFF + srow0 + j * 4] = h0a;
            sm[SS1_OFF + srow0 + j * 4] = h1a;
            sm[SS0_OFF + srow1 + j * 4] = h0b;
            sm[SS1_OFF + srow1 + j * 4] = h1b;
        }
        __syncthreads();

        // ---- ph3: Δ = s·MopNegᵀ ; cache s A-frags ----
        uint32_t s0[4][4], s1[4][4];
        #pragma unroll
        for (int kk = 0; kk < 4; kk++) {
            ldsm4(s0[kk], ss_a0 + kk * 32);
            ldsm4(s1[kk], ss_a1 + kk * 32);
        }

        const int last = (it == N_ITER - 1);
        #pragma unroll 1
        for (int jj = 0; jj < 4; jj++) {
            // 3 term-accumulator sets (6 distinct frags per kk)
            float u1[2][4], u2[2][4], u3[2][4];
            #pragma unroll
            for (int h = 0; h < 2; h++)
                #pragma unroll
                for (int k = 0; k < 4; k++) {
                    u1[h][k] = 0.0f; u2[h][k] = 0.0f; u3[h][k] = 0.0f;
                }

            #pragma unroll
            for (int kk = 0; kk < 4; kk++) {
                uint32_t m0[4], m1[4];
                ldsm4(m0, mt_b0 + (uint32_t)(jj * 16 * 36 * 4) + kk * 32);
                ldsm4(m1, mt_b1 + (uint32_t)(jj * 16 * 36 * 4) + kk * 32);
                mma16816(u1[0], s0[kk], m0[0], m0[1]);
                mma16816(u1[1], s0[kk], m0[2], m0[3]);
                mma16816(u2[0], s0[kk], m1[0], m1[1]);
                mma16816(u2[1], s0[kk], m1[2], m1[3]);
                mma16816(u3[0], s1[kk], m0[0], m0[1]);
                mma16816(u3[1], s1[kk], m0[2], m0[3]);
            }

            // ---- ph4 for ntiles j = 2jj, 2jj+1 ----
            #pragma unroll
            for (int h = 0; h < 2; h++) {
                const int j = 2 * jj + h;
                float yv[4];
                #pragma unroll
                for (int k = 0; k < 4; k++) {
                    float acc = u1[h][k] + u2[h][k] + u3[h][k];
                    float zv = zb[j][k];
                    float y = fmaf(0.5f, zv, acc);
                    float w = fmaxf(2.0f * y - zv + y0f[j][k], 0.0f);
                    zb[j][k] = fmaf(1.7f, w - y, zv);
                    yv[k] = y;
                }
                // re-split new zb -> smem
                uint32_t h0a = f16x2_rn(zb[j][0], zb[j][1]);
                float2 b0 = f16x2_back(h0a);
                uint32_t h1a = f16x2_rn(zb[j][0] - b0.x, zb[j][1] - b0.y);
                uint32_t h0b = f16x2_rn(zb[j][2], zb[j][3]);
                float2 b1 = f16x2_back(h0b);
                uint32_t h1b = f16x2_rn(zb[j][2] - b1.x, zb[j][3] - b1.y);
                sm[ZB0_OFF + zrow0 + j * 4] = h0a;
                sm[ZB1_OFF + zrow0 + j * 4] = h1a;
                sm[ZB0_OFF + zrow1 + j * 4] = h0b;
                sm[ZB1_OFF + zrow1 + j * 4] = h1b;
                if (last) {
                    *(float2*)(outp0 + j * 8 + 2 * t) = make_float2(yv[0], yv[1]);
                    *(float2*)(outp1 + j * 8 + 2 * t) = make_float2(yv[2], yv[3]);
                }
            }
        }
        __syncthreads();
    }
}

// ---------------------------------------------------------------------------
extern "C" void kernel_launch(void* const* d_in, const int* in_sizes, int n_in,
                              void* d_out, int out_size)
{
    const float* x    = (const float*)d_in[0];
    const float* bcon = (const float*)d_in[1];
    const float* A    = (const float*)d_in[2];
    const float* W1   = (const float*)d_in[3];
    const float* b1   = (const float*)d_in[4];
    const float* W2   = (const float*)d_in[5];
    const float* b2   = (const float*)d_in[6];
    const float* W3   = (const float*)d_in[7];
    const float* b3   = (const float*)d_in[8];
    const float* Wout = (const float*)d_in[9];
    const float* bout = (const float*)d_in[10];
    float* out = (float*)d_out;

    float *h1, *h2, *y0;
    cudaGetSymbolAddress((void**)&h1, g_h1);
    cudaGetSymbolAddress((void**)&h2, g_h2);
    cudaGetSymbolAddress((void**)&y0, g_y0);

    cudaFuncSetAttribute(iterate_mma,
                         cudaFuncAttributeMaxDynamicSharedMemorySize,
                         ITER_SMEM_BYTES);

    dim3 blk(256);
    // MLP trunk
    gemm_bias_act<<<dim3(H_DIM / 64, B_ROWS / 128), blk>>>(x,  W1, b1, h1, B_ROWS, H_DIM, DIM_IN, 1);
    gemm_bias_act<<<dim3(H_DIM / 64, B_ROWS / 128), blk>>>(h1, W2, b2, h2, B_ROWS, H_DIM, H_DIM, 1);
    gemm_bias_act<<<dim3(H_DIM / 64, B_ROWS / 128), blk>>>(h2, W3, b3, h1, B_ROWS, H_DIM, H_DIM, 1);
    gemm_bias_act<<<dim3(D_DIM / 64, B_ROWS / 128), blk>>>(h1, Wout, bout, y0, B_ROWS, D_DIM, H_DIM, 0);

    // projection operator setup (fused)
    setup_kernel<<<1, 256>>>(A);

    // 100 Douglas-Rachford iterations on tensor cores (mma.sync)
    iterate_mma<<<B_ROWS / 32, 256, ITER_SMEM_BYTES>>>(bcon, A, y0, out);
}

// round 14
// speedup vs baseline: 1.5487x; 1.0043x over previous
#include <cuda_runtime.h>
#include <cuda_fp16.h>
#include <cstdint>

// Problem constants (fixed by the dataset)
#define B_ROWS 4096
#define DIM_IN 128
#define H_DIM  512
#define D_DIM  256
#define M_CON  64
#define N_ITER 100

// Scratch (device globals: no allocation allowed)
__device__ float g_h1[B_ROWS * H_DIM];
__device__ float g_h2[B_ROWS * H_DIM];
__device__ float g_y0[B_ROWS * D_DIM];
__device__ float g_MopNeg[M_CON * D_DIM];   // -K A (pre-negated)

// ===========================================================================
// Warp MMA helpers (sm_75+ baseline: work on plain sm_103 target)
// ===========================================================================
__device__ __forceinline__ uint32_t smem_to_u32(const void* p) {
    uint32_t a;
    asm("{ .reg .u64 t; cvta.to.shared.u64 t, %1; cvt.u32.u64 %0, t; }"
        : "=r"(a) : "l"(p));
    return a;
}
__device__ __forceinline__ void ldsm4(uint32_t* r, uint32_t addr) {
    asm volatile("ldmatrix.sync.aligned.m8n8.x4.shared.b16 {%0,%1,%2,%3}, [%4];"
                 : "=r"(r[0]), "=r"(r[1]), "=r"(r[2]), "=r"(r[3]) : "r"(addr));
}
__device__ __forceinline__ void mma16816(float* c, const uint32_t* a,
                                         uint32_t b0, uint32_t b1) {
    asm volatile("mma.sync.aligned.m16n8k16.row.col.f32.f16.f16.f32 "
                 "{%0,%1,%2,%3}, {%4,%5,%6,%7}, {%8,%9}, {%0,%1,%2,%3};"
                 : "+f"(c[0]), "+f"(c[1]), "+f"(c[2]), "+f"(c[3])
                 : "r"(a[0]), "r"(a[1]), "r"(a[2]), "r"(a[3]), "r"(b0), "r"(b1));
}
__device__ __forceinline__ uint32_t f16x2_rn(float v0, float v1) {
    __half2 h = __floats2half2_rn(v0, v1);   // v0 -> low half
    return *(uint32_t*)&h;
}
__device__ __forceinline__ float2 f16x2_back(uint32_t u) {
    __half2 h = *(__half2*)&u;
    return __half22float2(h);
}

// smem map for the iterate kernel (u32 units). Row strides padded +4 u32 so
// ldmatrix row-gathers and fragment STS are bank-conflict-free.
// Per-half state buffers (half = 16 rows): zb splits + s splits.
#define ZB_BASE   0                        // half h: [h*4224 .. ): split0 [16][132], split1 [16][132]
#define ZB_HSTR   (2 * 16 * 132)           // 4224
#define ZB_S1     (16 * 132)               // 2112 (split1 offset within half)
#define SS_BASE   (2 * ZB_HSTR)            // 8448
#define SS_HSTR   (2 * 16 * 36)            // 1152
#define SS_S1     (16 * 36)                // 576
#define AT0_OFF   (SS_BASE + 2 * SS_HSTR)  // 10752: 0.5*A split0 [64 mi][264 f16] = [64][132]
#define AT1_OFF   (AT0_OFF + 64 * 132)     // 19200
#define MT0_OFF   (AT1_OFF + 64 * 132)     // 27648: MopNegT split0 [256 d][72 f16] = [256][36]
#define MT1_OFF   (MT0_OFF + 256 * 36)     // 36864
#define ITER_SMEM_U32 (MT1_OFF + 256 * 36) // 46080
#define ITER_SMEM_BYTES (ITER_SMEM_U32 * 4)   // 184320

// ===========================================================================
// Trunk SGEMM (best-known version): C = act(X @ W + bias)
// ===========================================================================
__device__ __forceinline__ unsigned long long dup2(float v) {
    unsigned long long r;
    asm("mov.b64 %0, {%1, %1};" : "=l"(r) : "f"(v));
    return r;
}
__device__ __forceinline__ void fma2(unsigned long long& d,
                                     unsigned long long a, unsigned long long b) {
    asm("fma.rn.f32x2 %0, %1, %2, %0;" : "+l"(d) : "l"(a), "l"(b));
}
__device__ __forceinline__ void unpack2(unsigned long long v, float& lo, float& hi) {
    asm("mov.b64 {%0, %1}, %2;" : "=f"(lo), "=f"(hi) : "l"(v));
}

__global__ __launch_bounds__(256) void gemm_bias_act(
    const float* __restrict__ X, const float* __restrict__ W,
    const float* __restrict__ bias, float* __restrict__ C,
    int M, int N, int K, int doRelu)
{
    __shared__ float Xs[16][128];
    __shared__ float Ws[16][64];

    const int tid  = threadIdx.x;
    const int brow = blockIdx.y * 128;
    const int bcol = blockIdx.x * 64;
    const int tx   = tid & 15;
    const int ty   = tid >> 4;
    const int xr0 = tid >> 2;
    const int xc0 = (tid & 3) * 4;
    const int wr0 = tid >> 4;
    const int wc0 = (tid & 15) * 4;

    unsigned long long acc2[8][2];
    #pragma unroll
    for (int i = 0; i < 8; i++) { acc2[i][0] = 0ULL; acc2[i][1] = 0ULL; }

    for (int kt = 0; kt < K; kt += 16) {
        float4 xv0 = *(const float4*)&X[(size_t)(brow + xr0) * K + kt + xc0];
        float4 xv1 = *(const float4*)&X[(size_t)(brow + xr0 + 64) * K + kt + xc0];
        float4 wv  = *(const float4*)&W[(size_t)(kt + wr0) * N + bcol + wc0];

        Xs[xc0 + 0][xr0] = xv0.x;  Xs[xc0 + 1][xr0] = xv0.y;
        Xs[xc0 + 2][xr0] = xv0.z;  Xs[xc0 + 3][xr0] = xv0.w;
        Xs[xc0 + 0][xr0 + 64] = xv1.x;  Xs[xc0 + 1][xr0 + 64] = xv1.y;
        Xs[xc0 + 2][xr0 + 64] = xv1.z;  Xs[xc0 + 3][xr0 + 64] = xv1.w;
        *(float4*)&Ws[wr0][wc0] = wv;
        __syncthreads();

        #pragma unroll
        for (int k = 0; k < 16; k++) {
            float a[8];
            float4 a0 = *(const float4*)&Xs[k][ty * 8];
            float4 a1 = *(const float4*)&Xs[k][ty * 8 + 4];
            a[0]=a0.x; a[1]=a0.y; a[2]=a0.z; a[3]=a0.w;
            a[4]=a1.x; a[5]=a1.y; a[6]=a1.z; a[7]=a1.w;
            ulonglong2 bv = *(const ulonglong2*)&Ws[k][tx * 4];
            #pragma unroll
            for (int i = 0; i < 8; i++) {
                unsigned long long ad = dup2(a[i]);
                fma2(acc2[i][0], ad, bv.x);
                fma2(acc2[i][1], ad, bv.y);
            }
        }
        __syncthreads();
    }

    const int col = bcol + tx * 4;
    float4 bb = *(const float4*)&bias[col];
    #pragma unroll
    for (int i = 0; i < 8; i++) {
        int row = brow + ty * 8 + i;
        float4 v;
        unpack2(acc2[i][0], v.x, v.y);
        unpack2(acc2[i][1], v.z, v.w);
        v.x += bb.x; v.y += bb.y; v.z += bb.z; v.w += bb.w;
        if (doRelu) {
            v.x = fmaxf(v.x, 0.0f); v.y = fmaxf(v.y, 0.0f);
            v.z = fmaxf(v.z, 0.0f); v.w = fmaxf(v.w, 0.0f);
        }
        *(float4*)&C[(size_t)row * N + col] = v;
    }
}

// ===========================================================================
// Fused setup (single block): G = A Aᵀ -> Gauss-Jordan inverse -> MopNeg = -K A
// ===========================================================================
__global__ __launch_bounds__(256) void setup_kernel(const float* __restrict__ A)
{
    __shared__ float Wk[M_CON][2 * M_CON];
    __shared__ float fcol[M_CON];
    const int tid = threadIdx.x;

    for (int idx = tid; idx < M_CON * M_CON; idx += 256) {
        int r = idx >> 6, c = idx & 63;
        float s = 0.0f;
        for (int d = 0; d < D_DIM; d++)
            s = fmaf(A[r * D_DIM + d], A[c * D_DIM + d], s);
        Wk[r][c] = s;
        Wk[r][M_CON + c] = (r == c) ? 1.0f : 0.0f;
    }
    __syncthreads();

    for (int k = 0; k < M_CON; k++) {
        if (tid < M_CON) fcol[tid] = Wk[tid][k];
        __syncthreads();
        float pivinv = 1.0f / fcol[k];
        if (tid < 2 * M_CON) Wk[k][tid] *= pivinv;
        __syncthreads();
        for (int idx = tid; idx < M_CON * 2 * M_CON; idx += 256) {
            int r = idx >> 7, c = idx & 127;
            if (r != k) Wk[r][c] = fmaf(-fcol[r], Wk[k][c], Wk[r][c]);
        }
        __syncthreads();
    }

    for (int idx = tid; idx < M_CON * D_DIM; idx += 256) {
        int m = idx >> 8, d = idx & 255;
        float s = 0.0f;
        #pragma unroll 8
        for (int j = 0; j < M_CON; j++)
            s = fmaf(Wk[m][M_CON + j], A[j * D_DIM + d], s);
        g_MopNeg[idx] = -s;
    }
}

// ===========================================================================
// HMMA DR iteration kernel — two independent pipelined halves per block.
// grid=128, 32 rows/block, 256 threads (8 warps).
// half = wid>>2 owns rows half*16..half*16+15 with its OWN zb/s smem buffers
// and its OWN named barrier (bar.sync half+1, 128) -> the two halves drift
// out of phase, so one half's MMAs cover the other's epilogue/barrier/ldsm
// gaps on the shared tensor pipe.
// Within a half, warp c = wid&3 owns: ph2 m-cols c*16..+15, ph3/state
// d-cols c*64..+63. Per-warp fragment math identical to R13 (validated).
// ===========================================================================
__global__ __launch_bounds__(256, 1) void iterate_mma(
    const float* __restrict__ bcon, const float* __restrict__ A,
    const float* __restrict__ y0g, float* __restrict__ out)
{
    extern __shared__ uint32_t sm[];
    const uint32_t sb = smem_to_u32(sm);
    const int tid  = threadIdx.x;
    const int lane = tid & 31;
    const int wid  = tid >> 5;
    const int half = wid >> 2;     // 0/1: rows half*16 .. half*16+15
    const int c    = wid & 3;      // quarter: ph2 m-cols c*16.., ph3 d-cols c*64..

    // ---- constant tiles: fp16 2-term splits (block-wide staging) ----
    for (int i = tid; i < M_CON * D_DIM; i += 256) {
        int mi = i >> 8, d = i & 255;
        float v = 0.5f * A[i];
        __half h0 = __float2half_rn(v);
        __half h1 = __float2half_rn(v - __half2float(h0));
        ((__half*)(sm + AT0_OFF))[mi * 264 + d] = h0;
        ((__half*)(sm + AT1_OFF))[mi * 264 + d] = h1;
    }
    for (int i = tid; i < M_CON * D_DIM; i += 256) {
        int m = i >> 8, d = i & 255;
        float v = g_MopNeg[i];
        __half h0 = __float2half_rn(v);
        __half h1 = __float2half_rn(v - __half2float(h0));
        ((__half*)(sm + MT0_OFF))[d * 72 + m] = h0;
        ((__half*)(sm + MT1_OFF))[d * 72 + m] = h1;
    }

    // ---- fragment geometry ----
    const int g = lane >> 2, t = lane & 3;          // C-frag: rows g,g+8; cols 2t,2t+1
    const int mat = lane >> 3, lrow = lane & 7;     // ldmatrix lane mapping
    const int arow  = ((mat & 1) << 3) + lrow;      // A-op: row within 16
    const int akoff = (mat >> 1) << 3;              //       k half (f16 units)
    const int bnrow = ((lane >> 4) << 3) + lrow;    // B-op: n row
    const int bkoff = ((lane >> 3) & 1) << 3;       //       k half

    const uint32_t zb_a0 = sb + 4 * (ZB_BASE + half * ZB_HSTR + arow * 132 + (akoff >> 1));
    const uint32_t zb_a1 = zb_a0 + 4 * ZB_S1;
    const uint32_t at_b0 = sb + 4 * (AT0_OFF + (c * 16 + bnrow) * 132 + (bkoff >> 1));
    const uint32_t at_b1 = at_b0 + 4 * (64 * 132);
    const uint32_t ss_a0 = sb + 4 * (SS_BASE + half * SS_HSTR + arow * 36 + (akoff >> 1));
    const uint32_t ss_a1 = ss_a0 + 4 * SS_S1;
    const uint32_t mt_b0 = sb + 4 * (MT0_OFF + (c * 64 + bnrow) * 36 + (bkoff >> 1));
    const uint32_t mt_b1 = mt_b0 + 4 * (256 * 36);

    // STS bases (u32 index): rows g / g+8 of this half
    const int zrow0 = ZB_BASE + half * ZB_HSTR + g * 36 * 0 + g * 132 + c * 32 + t;
    const int zrow1 = zrow0 + 8 * 132;
    const int srow0 = SS_BASE + half * SS_HSTR + g * 36 + c * 8 + t;
    const int srow1 = srow0 + 8 * 36;

    // ---- state fragments ----
    const int row0 = blockIdx.x * 32 + half * 16;
    const float* y0p0 = y0g + (size_t)(row0 + g) * D_DIM + c * 64;
    const float* y0p1 = y0g + (size_t)(row0 + 8 + g) * D_DIM + c * 64;
    const float* bcp0 = bcon + (size_t)(row0 + g) * M_CON + c * 16;
    const float* bcp1 = bcon + (size_t)(row0 + 8 + g) * M_CON + c * 16;

    float zb[8][4], y0f[8][4], nbcf[2][4];
    #pragma unroll
    for (int j = 0; j < 8; j++) {
        float2 u = *(const float2*)(y0p0 + j * 8 + 2 * t);
        float2 v = *(const float2*)(y0p1 + j * 8 + 2 * t);
        y0f[j][0] = u.x; y0f[j][1] = u.y; y0f[j][2] = v.x; y0f[j][3] = v.y;
        zb[j][0] = 2.0f * u.x; zb[j][1] = 2.0f * u.y;
        zb[j][2] = 2.0f * v.x; zb[j][3] = 2.0f * v.y;
    }
    #pragma unroll
    for (int j = 0; j < 2; j++) {
        float2 u = *(const float2*)(bcp0 + j * 8 + 2 * t);
        float2 v = *(const float2*)(bcp1 + j * 8 + 2 * t);
        nbcf[j][0] = -u.x; nbcf[j][1] = -u.y; nbcf[j][2] = -v.x; nbcf[j][3] = -v.y;
    }

    // initial zb split -> smem
    #pragma unroll
    for (int j = 0; j < 8; j++) {
        uint32_t h0a = f16x2_rn(zb[j][0], zb[j][1]);
        float2 b0 = f16x2_back(h0a);
        uint32_t h1a = f16x2_rn(zb[j][0] - b0.x, zb[j][1] - b0.y);
        uint32_t h0b = f16x2_rn(zb[j][2], zb[j][3]);
        float2 b1 = f16x2_back(h0b);
        uint32_t h1b = f16x2_rn(zb[j][2] - b1.x, zb[j][3] - b1.y);
        sm[zrow0 + j * 4] = h0a;
        sm[zrow0 + ZB_S1 + j * 4] = h1a;
        sm[zrow1 + j * 4] = h0b;
        sm[zrow1 + ZB_S1 + j * 4] = h1b;
    }
    __syncthreads();   // tiles + initial zb of both halves visible

    float* outp0 = out + (size_t)(row0 + g) * D_DIM + c * 64;
    float* outp1 = out + (size_t)(row0 + 8 + g) * D_DIM + c * 64;
    const uint32_t barid = half + 1;

    #pragma unroll 1
    for (int it = 0; it < N_ITER; it++) {
        // ---- ph2: s = zb·(0.5A)ᵀ - bc, 3 term-accumulator sets ----
        float t1[2][4], t2[2][4], t3[2][4];
        #pragma unroll
        for (int j = 0; j < 2; j++)
            #pragma unroll
            for (int k = 0; k < 4; k++) {
                t1[j][k] = nbcf[j][k]; t2[j][k] = 0.0f; t3[j][k] = 0.0f;
            }

        #pragma unroll 4
        for (int kk = 0; kk < 16; kk++) {
            uint32_t za[4], zc[4], ba[4], bb2[4];
            ldsm4(za, zb_a0 + kk * 32);
            ldsm4(zc, zb_a1 + kk * 32);
            ldsm4(ba, at_b0 + kk * 32);
            ldsm4(bb2, at_b1 + kk * 32);
            mma16816(t1[0], za, ba[0], ba[1]);
            mma16816(t1[1], za, ba[2], ba[3]);
            mma16816(t2[0], za, bb2[0], bb2[1]);
            mma16816(t2[1], za, bb2[2], bb2[3]);
            mma16816(t3[0], zc, ba[0], ba[1]);
            mma16816(t3[1], zc, ba[2], ba[3]);
        }

        // merge terms + s split -> smem
        #pragma unroll
        for (int j = 0; j < 2; j++) {
            float v0 = t1[j][0] + t2[j][0] + t3[j][0];
            float v1 = t1[j][1] + t2[j][1] + t3[j][1];
            float v2 = t1[j][2] + t2[j][2] + t3[j][2];
            float v3 = t1[j][3] + t2[j][3] + t3[j][3];
            uint32_t h0a = f16x2_rn(v0, v1);
            float2 b0 = f16x2_back(h0a);
            uint32_t h1a = f16x2_rn(v0 - b0.x, v1 - b0.y);
            uint32_t h0b = f16x2_rn(v2, v3);
            float2 b1 = f16x2_back(h0b);
            uint32_t h1b = f16x2_rn(v2 - b1.x, v3 - b1.y);
            sm[srow0 + j * 4] = h0a;
            sm[srow0 + SS_S1 + j * 4] = h1a;
            sm[srow1 + j * 4] = h0b;
            sm[srow1 + SS_S1 + j * 4] = h1b;
        }
        asm volatile("bar.sync %0, 128;" :: "r"(barid) : "memory");

        // ---- ph3: Δ = s·MopNegᵀ ; cache s A-frags ----
        uint32_t s0[4][4], s1[4][4];
        #pragma unroll
        for (int kk = 0; kk < 4; kk++) {
            ldsm4(s0[kk], ss_a0 + kk * 32);
            ldsm4(s1[kk], ss_a1 + kk * 32);
        }

        const int last = (it == N_ITER - 1);
        #pragma unroll
        for (int jj = 0; jj < 4; jj++) {
            float u1[2][4], u2[2][4], u3[2][4];
            #pragma unroll
            for (int h = 0; h < 2; h++)
                #pragma unroll
                for (int k = 0; k < 4; k++) {
                    u1[h][k] = 0.0f; u2[h][k] = 0.0f; u3[h][k] = 0.0f;
                }

            #pragma unroll
            for (int kk = 0; kk < 4; kk++) {
                uint32_t m0[4], m1[4];
                ldsm4(m0, mt_b0 + (uint32_t)(jj * 16 * 36 * 4) + kk * 32);
                ldsm4(m1, mt_b1 + (uint32_t)(jj * 16 * 36 * 4) + kk * 32);
                mma16816(u1[0], s0[kk], m0[0], m0[1]);
                mma16816(u1[1], s0[kk], m0[2], m0[3]);
                mma16816(u2[0], s0[kk], m1[0], m1[1]);
                mma16816(u2[1], s0[kk], m1[2], m1[3]);
                mma16816(u3[0], s1[kk], m0[0], m0[1]);
                mma16816(u3[1], s1[kk], m0[2], m0[3]);
            }

            // ---- ph4 for ntiles j = 2jj, 2jj+1 ----
            #pragma unroll
            for (int h = 0; h < 2; h++) {
                const int j = 2 * jj + h;
                float yv[4];
                #pragma unroll
                for (int k = 0; k < 4; k++) {
                    float acc = u1[h][k] + u2[h][k] + u3[h][k];
                    float zv = zb[j][k];
                    float y = fmaf(0.5f, zv, acc);
                    float w = fmaxf(2.0f * y - zv + y0f[j][k], 0.0f);
                    zb[j][k] = fmaf(1.7f, w - y, zv);
                    yv[k] = y;
                }
                // re-split new zb -> smem
                uint32_t h0a = f16x2_rn(zb[j][0], zb[j][1]);
                float2 b0 = f16x2_back(h0a);
                uint32_t h1a = f16x2_rn(zb[j][0] - b0.x, zb[j][1] - b0.y);
                uint32_t h0b = f16x2_rn(zb[j][2], zb[j][3]);
                float2 b1 = f16x2_back(h0b);
                uint32_t h1b = f16x2_rn(zb[j][2] - b1.x, zb[j][3] - b1.y);
                sm[zrow0 + j * 4] = h0a;
                sm[zrow0 + ZB_S1 + j * 4] = h1a;
                sm[zrow1 + j * 4] = h0b;
                sm[zrow1 + ZB_S1 + j * 4] = h1b;
                if (last) {
                    *(float2*)(outp0 + j * 8 + 2 * t) = make_float2(yv[0], yv[1]);
                    *(float2*)(outp1 + j * 8 + 2 * t) = make_float2(yv[2], yv[3]);
                }
            }
        }
        asm volatile("bar.sync %0, 128;" :: "r"(barid) : "memory");
    }
}

// ---------------------------------------------------------------------------
extern "C" void kernel_launch(void* const* d_in, const int* in_sizes, int n_in,
                              void* d_out, int out_size)
{
    const float* x    = (const float*)d_in[0];
    const float* bcon = (const float*)d_in[1];
    const float* A    = (const float*)d_in[2];
    const float* W1   = (const float*)d_in[3];
    const float* b1   = (const float*)d_in[4];
    const float* W2   = (const float*)d_in[5];
    const float* b2   = (const float*)d_in[6];
    const float* W3   = (const float*)d_in[7];
    const float* b3   = (const float*)d_in[8];
    const float* Wout = (const float*)d_in[9];
    const float* bout = (const float*)d_in[10];
    float* out = (float*)d_out;

    float *h1, *h2, *y0;
    cudaGetSymbolAddress((void**)&h1, g_h1);
    cudaGetSymbolAddress((void**)&h2, g_h2);
    cudaGetSymbolAddress((void**)&y0, g_y0);

    cudaFuncSetAttribute(iterate_mma,
                         cudaFuncAttributeMaxDynamicSharedMemorySize,
                         ITER_SMEM_BYTES);

    dim3 blk(256);
    // MLP trunk
    gemm_bias_act<<<dim3(H_DIM / 64, B_ROWS / 128), blk>>>(x,  W1, b1, h1, B_ROWS, H_DIM, DIM_IN, 1);
    gemm_bias_act<<<dim3(H_DIM / 64, B_ROWS / 128), blk>>>(h1, W2, b2, h2, B_ROWS, H_DIM, H_DIM, 1);
    gemm_bias_act<<<dim3(H_DIM / 64, B_ROWS / 128), blk>>>(h2, W3, b3, h1, B_ROWS, H_DIM, H_DIM, 1);
    gemm_bias_act<<<dim3(D_DIM / 64, B_ROWS / 128), blk>>>(h1, Wout, bout, y0, B_ROWS, D_DIM, H_DIM, 0);

    // projection operator setup (fused)
    setup_kernel<<<1, 256>>>(A);

    // 100 Douglas-Rachford iterations on tensor cores (mma.sync, 2 pipelined halves)
    iterate_mma<<<B_ROWS / 32, 256, ITER_SMEM_BYTES>>>(bcon, A, y0, out);
}